// round 2
// baseline (speedup 1.0000x reference)
#include <cuda_runtime.h>

#define B_ 4
#define N_ 2048
#define V_ 12
#define C_ 50
#define P_ 16384   /* H*W = 128*128 */
#define RS_ 56     /* scratch row stride in floats: 224 B = 7 aligned sectors */

// Winner keys, encoded key+1 so 0 == "no winner". Statically zero-initialized;
// lift_gather resets each entry to 0 after reading, so every graph replay
// (and the first call) starts from a clean state without an init kernel.
__device__ int g_winner[B_ * V_ * N_];

// Per-(bv,pixel) finished weighted probabilities (w_v * softmax), written only
// for pixels that pass the mask (~7%), read only for winning pixels.
__device__ float g_feat[(size_t)B_ * V_ * P_ * RS_];   // ~176 MB

// One thread per pixel: coalesced read of 50 logits (stride P), argmax in
// registers; only mask-passing pixels pay for exp + contiguous 200B row store
// + atomicMax scatter.
__global__ __launch_bounds__(256) void argmax_scatter_kernel(
    const float* __restrict__ pred,        // (B,V,C,P)
    const int*   __restrict__ p2p,         // (B,V,P)
    const float* __restrict__ vw,          // (B,V)
    const int*   __restrict__ parts_nb)    // (B,)
{
    int t = blockIdx.x * blockDim.x + threadIdx.x;
    if (t >= B_ * V_ * P_) return;
    int bv = t / P_;
    int p  = t - bv * P_;
    int b  = bv / V_;

    int point = p2p[t];
    if (point < 0) return;                 // invalid pixel

    const float* base = pred + (size_t)bv * C_ * P_ + p;
    float x[C_];
    float mx = -3.402823466e+38f;
    int   am = 0;
#pragma unroll
    for (int c = 0; c < C_; c++) {
        x[c] = base[(size_t)c * P_];
        if (x[c] > mx) { mx = x[c]; am = c; }   // '>' keeps first occurrence (jnp.argmax)
    }

    int pn = parts_nb[b];
    if (am >= 1 && am <= pn) {
        float se = 0.f;
#pragma unroll
        for (int c = 0; c < C_; c++) { x[c] = expf(x[c] - mx); se += x[c]; }
        float scale = vw[bv] / se;

        // Contiguous, 16B-aligned row of finished weighted probs.
        float* row = g_feat + (size_t)t * RS_;
        float4* r4 = (float4*)row;
#pragma unroll
        for (int c4 = 0; c4 < C_ / 4; c4++)    // 48 floats as float4
            r4[c4] = make_float4(x[4*c4+0]*scale, x[4*c4+1]*scale,
                                 x[4*c4+2]*scale, x[4*c4+3]*scale);
        row[48] = x[48] * scale;
        row[49] = x[49] * scale;

        int key = am * P_ + p + 1;             // +1: 0 means "no winner"
        atomicMax(&g_winner[bv * N_ + (point & (N_ - 1))], key);
    }
}

// One block per (b, n). Threads 0..V-1 stage winner rows (and reset the winner
// slot for the next replay); threads 0..C-1 sum contiguous weighted-prob rows.
__global__ __launch_bounds__(64) void lift_gather_kernel(
    float* __restrict__ out)               // (B,C,N)
{
    int bn = blockIdx.x;
    int b  = bn / N_;
    int n  = bn - b * N_;
    int tid = threadIdx.x;

    __shared__ const float* s_row[V_];
    __shared__ int s_cnt;

    if (tid == 0) s_cnt = 0;
    __syncthreads();

    if (tid < V_) {
        int* wp = &g_winner[(b * V_ + tid) * N_ + n];
        int key = *wp;
        *wp = 0;                               // reset for next graph replay
        if (key > 0) {
            int pix = (key - 1) & (P_ - 1);
            s_row[tid] = g_feat + ((size_t)(b * V_ + tid) * P_ + pix) * RS_;
            atomicAdd(&s_cnt, 1);
        } else {
            s_row[tid] = nullptr;
        }
    }
    __syncthreads();

    if (tid >= C_) return;

    float acc = 0.f;
#pragma unroll
    for (int v = 0; v < V_; v++) {
        const float* row = s_row[v];
        if (row) acc += row[tid];
    }
    float denom = fmaxf((float)s_cnt, 1.f);
    out[((size_t)b * C_ + tid) * N_ + n] = acc / denom;
}

extern "C" void kernel_launch(void* const* d_in, const int* in_sizes, int n_in,
                              void* d_out, int out_size) {
    // inputs: 0 points (unused), 1 predictions_2d, 2 rendered_pix_to_point,
    //         3 views_weights, 4 parts_nb
    const float* pred     = (const float*)d_in[1];
    const int*   p2p      = (const int*)  d_in[2];
    const float* vw       = (const float*)d_in[3];
    const int*   parts_nb = (const int*)  d_in[4];
    float*       out      = (float*)d_out;

    argmax_scatter_kernel<<<(B_ * V_ * P_ + 255) / 256, 256>>>(pred, p2p, vw, parts_nb);
    lift_gather_kernel<<<B_ * N_, 64>>>(out);
}

// round 3
// speedup vs baseline: 1.4395x; 1.4395x over previous
#include <cuda_runtime.h>

#define B_  4
#define N_  2048
#define V_  12
#define C_  50
#define P_  16384   /* H*W = 128*128 */
#define RSL 6       /* log2 row stride: 64 floats = 256 B aligned rows */
#define GN_ 8       /* n-items per gather block (= warps per block) */

// Winner keys, encoded key+1 so 0 == "no winner". Statically zero-initialized;
// lift_gather resets each entry to 0 after reading -> clean state every replay.
__device__ int g_winner[B_ * V_ * N_];

// Per-(bv,pixel) finished weighted probabilities (w_v * softmax), 256B rows.
// Columns 50..63 are never written -> stay zero forever (safe to read).
__device__ float g_feat[((size_t)B_ * V_ * P_) << RSL];   // ~201 MB
// Never written -> always zero. Target for views without a winner.
__device__ float g_zero[1 << RSL];

// One thread per pixel: coalesced read of 50 logits (stride P), argmax in
// registers; only mask-passing pixels (~7%) pay exp + 200B row store + atomic.
__global__ __launch_bounds__(256) void argmax_scatter_kernel(
    const float* __restrict__ pred,        // (B,V,C,P)
    const int*   __restrict__ p2p,         // (B,V,P)
    const float* __restrict__ vw,          // (B,V)
    const int*   __restrict__ parts_nb)    // (B,)
{
    int t = blockIdx.x * blockDim.x + threadIdx.x;
    if (t >= B_ * V_ * P_) return;
    int bv = t / P_;
    int p  = t - bv * P_;
    int b  = bv / V_;

    int point = p2p[t];
    if (point < 0) return;                 // invalid pixel

    const float* base = pred + (size_t)bv * C_ * P_ + p;
    float x[C_];
    float mx = -3.402823466e+38f;
    int   am = 0;
#pragma unroll
    for (int c = 0; c < C_; c++) {
        x[c] = base[(size_t)c * P_];
        if (x[c] > mx) { mx = x[c]; am = c; }   // '>' keeps first occurrence (jnp.argmax)
    }

    int pn = parts_nb[b];
    if (am >= 1 && am <= pn) {
        float se = 0.f;
#pragma unroll
        for (int c = 0; c < C_; c++) { x[c] = __expf(x[c] - mx); se += x[c]; }
        float scale = vw[bv] / se;

        float* row = g_feat + ((size_t)t << RSL);   // 256B-aligned row
        float4* r4 = (float4*)row;
#pragma unroll
        for (int c4 = 0; c4 < C_ / 4; c4++)
            r4[c4] = make_float4(x[4*c4+0]*scale, x[4*c4+1]*scale,
                                 x[4*c4+2]*scale, x[4*c4+3]*scale);
        row[48] = x[48] * scale;
        row[49] = x[49] * scale;

        int key = am * P_ + p + 1;             // +1: 0 means "no winner"
        atomicMax(&g_winner[bv * N_ + (point & (N_ - 1))], key);
    }
}

// One WARP per (b,n), 8 warps/block over consecutive n. Branchless: views
// without a winner read g_zero. All 24 row loads per warp are independent ->
// front-batched LDGs (high MLP). Output staged through smem for coalesced
// (B,C,N) writes.
__global__ __launch_bounds__(256) void lift_gather_kernel(
    float* __restrict__ out)               // (B,C,N)
{
    int blk  = blockIdx.x;
    int b    = blk / (N_ / GN_);
    int n0   = (blk - b * (N_ / GN_)) * GN_;
    int wid  = threadIdx.x >> 5;
    int lane = threadIdx.x & 31;
    int n    = n0 + wid;

    __shared__ float s_acc[C_][GN_ + 1];   // +1 pad: conflict-free transpose
    __shared__ float s_dn[GN_];

    // Lanes 0..V-1 read (and reset) winner keys for their view.
    int key = 0;
    if (lane < V_) {
        int* wp = &g_winner[(b * V_ + lane) * N_ + n];
        key = *wp;
        *wp = 0;                           // reset for next graph replay
    }
    unsigned ball = __ballot_sync(0xFFFFFFFFu, key > 0);
    float denom = fmaxf((float)__popc(ball), 1.f);

    float acc0 = 0.f, acc1 = 0.f;
#pragma unroll
    for (int v = 0; v < V_; v++) {
        int kv = __shfl_sync(0xFFFFFFFFu, key, v);
        const float* row = (kv > 0)
            ? g_feat + (((size_t)(b * V_ + v) * P_ + ((kv - 1) & (P_ - 1))) << RSL)
            : g_zero;
        acc0 += row[lane];                 // c = lane
        acc1 += row[lane + 32];            // c = lane+32 (pad cols are 0)
    }

    s_acc[lane][wid] = acc0;
    if (lane + 32 < C_) s_acc[lane + 32][wid] = acc1;
    if (lane == 0) s_dn[wid] = denom;
    __syncthreads();

    // 400 outputs per block, coalesced along n.
#pragma unroll
    for (int i = threadIdx.x; i < C_ * GN_; i += 256) {
        int c = i >> 3, j = i & (GN_ - 1);
        out[((size_t)b * C_ + c) * N_ + n0 + j] = s_acc[c][j] / s_dn[j];
    }
}

extern "C" void kernel_launch(void* const* d_in, const int* in_sizes, int n_in,
                              void* d_out, int out_size) {
    // inputs: 0 points (unused), 1 predictions_2d, 2 rendered_pix_to_point,
    //         3 views_weights, 4 parts_nb
    const float* pred     = (const float*)d_in[1];
    const int*   p2p      = (const int*)  d_in[2];
    const float* vw       = (const float*)d_in[3];
    const int*   parts_nb = (const int*)  d_in[4];
    float*       out      = (float*)d_out;

    argmax_scatter_kernel<<<(B_ * V_ * P_ + 255) / 256, 256>>>(pred, p2p, vw, parts_nb);
    lift_gather_kernel<<<(B_ * N_) / GN_, 256>>>(out);
}